// round 6
// baseline (speedup 1.0000x reference)
#include <cuda_runtime.h>
#include <cuda_fp16.h>
#include <math.h>
#include <stdint.h>

#define BC    2
#define SEQ   4096
#define NH    16
#define NKH   4
#define HDIM  128
#define DM    2048
#define WIN   512
#define NROT  64
#define MTOT  (BC*SEQ)   // 8192

// ---------------- scratch (device globals) ----------------
__device__ float g_q  [MTOT*NH*HDIM];
__device__ float g_k  [MTOT*NKH*HDIM];
__device__ float g_v  [MTOT*NKH*HDIM];
__device__ float g_cos[SEQ*NROT];
__device__ float g_sin[SEQ*NROT];

__device__ __half g_xn_hi[MTOT*DM];
__device__ __half g_xn_lo[MTOT*DM];
__device__ __half g_ao_hi[MTOT*NH*HDIM];
__device__ __half g_ao_lo[MTOT*NH*HDIM];
__device__ __half g_wqT[DM*DM];
__device__ __half g_wkT[(NKH*HDIM)*DM];
__device__ __half g_wvT[(NKH*HDIM)*DM];
__device__ __half g_woT[DM*DM];

// ================= low-level helpers =================
__device__ __forceinline__ uint32_t smem_to_u32(const void* p) {
    uint32_t a;
    asm("{ .reg .u64 t; cvta.to.shared.u64 t, %1; cvt.u32.u64 %0, t; }" : "=r"(a) : "l"(p));
    return a;
}
__device__ __forceinline__ void cp_async16(uint32_t dst, const void* src) {
    asm volatile("cp.async.cg.shared.global [%0], [%1], 16;" :: "r"(dst), "l"(src) : "memory");
}
#define CP_COMMIT() asm volatile("cp.async.commit_group;" ::: "memory")
#define CP_WAIT(n)  asm volatile("cp.async.wait_group %0;" :: "n"(n) : "memory")

__device__ __forceinline__ void ldm_x4(uint32_t* r, uint32_t addr) {
    asm volatile("ldmatrix.sync.aligned.m8n8.x4.shared.b16 {%0,%1,%2,%3}, [%4];"
        : "=r"(r[0]), "=r"(r[1]), "=r"(r[2]), "=r"(r[3]) : "r"(addr));
}
__device__ __forceinline__ void ldm_x4_t(uint32_t* r, uint32_t addr) {
    asm volatile("ldmatrix.sync.aligned.m8n8.x4.trans.shared.b16 {%0,%1,%2,%3}, [%4];"
        : "=r"(r[0]), "=r"(r[1]), "=r"(r[2]), "=r"(r[3]) : "r"(addr));
}
__device__ __forceinline__ void mma16816(float* d, const uint32_t* a, const uint32_t* b) {
    asm volatile("mma.sync.aligned.m16n8k16.row.col.f32.f16.f16.f32 "
        "{%0,%1,%2,%3}, {%4,%5,%6,%7}, {%8,%9}, {%0,%1,%2,%3};"
        : "+f"(d[0]), "+f"(d[1]), "+f"(d[2]), "+f"(d[3])
        : "r"(a[0]), "r"(a[1]), "r"(a[2]), "r"(a[3]), "r"(b[0]), "r"(b[1]));
}
__device__ __forceinline__ uint32_t pack_h2(__half a, __half b) {
    __half2 h = __halves2half2(a, b);
    return *(uint32_t*)&h;
}

// fp16 hi/lo split store
__device__ __forceinline__ void split_store_h(__half2* oh, __half2* ol, int idx2, float a, float b) {
    __half ah = __float2half_rn(a), bh = __float2half_rn(b);
    oh[idx2] = __halves2half2(ah, bh);
    ol[idx2] = __halves2half2(__float2half_rn(a - __half2float(ah)),
                              __float2half_rn(b - __half2float(bh)));
}

// ---------------- RMSNorm: one CTA per row; writes hi/lo fp16 ----------------
__global__ __launch_bounds__(256) void rmsnorm_kernel(const float* __restrict__ x,
                                                      const float* __restrict__ w) {
    int row = blockIdx.x;
    const float4* xr = (const float4*)(x + (size_t)row * DM);
    float4 v0 = xr[threadIdx.x];
    float4 v1 = xr[threadIdx.x + 256];
    float ss = v0.x*v0.x + v0.y*v0.y + v0.z*v0.z + v0.w*v0.w
             + v1.x*v1.x + v1.y*v1.y + v1.z*v1.z + v1.w*v1.w;
    #pragma unroll
    for (int off = 16; off > 0; off >>= 1) ss += __shfl_xor_sync(0xffffffffu, ss, off);
    __shared__ float red[8];
    if ((threadIdx.x & 31) == 0) red[threadIdx.x >> 5] = ss;
    __syncthreads();
    float tot = 0.f;
    #pragma unroll
    for (int i = 0; i < 8; i++) tot += red[i];
    float scl = rsqrtf(tot * (1.0f/DM) + 1e-6f);
    const float4* wr = (const float4*)w;
    float4 w0 = wr[threadIdx.x];
    float4 w1 = wr[threadIdx.x + 256];
    __half2* oh = (__half2*)(g_xn_hi + (size_t)row * DM);
    __half2* ol = (__half2*)(g_xn_lo + (size_t)row * DM);
    split_store_h(oh, ol, 2*threadIdx.x,   v0.x*scl*w0.x, v0.y*scl*w0.y);
    split_store_h(oh, ol, 2*threadIdx.x+1, v0.z*scl*w0.z, v0.w*scl*w0.w);
    split_store_h(oh, ol, 2*(threadIdx.x+256),   v1.x*scl*w1.x, v1.y*scl*w1.y);
    split_store_h(oh, ol, 2*(threadIdx.x+256)+1, v1.z*scl*w1.z, v1.w*scl*w1.w);
}

// ---------------- weight transpose to fp16: W[K][N] -> WT[N][K] ----------------
__global__ __launch_bounds__(256) void wtrans_kernel(const float* __restrict__ W,
                                                     __half* __restrict__ Th,
                                                     int K, int N) {
    __shared__ float s[32][33];
    int tx = threadIdx.x & 31, ty = threadIdx.x >> 5;
    int n0 = blockIdx.x * 32, k0 = blockIdx.y * 32;
    #pragma unroll
    for (int i = 0; i < 4; i++)
        s[ty + i*8][tx] = W[(size_t)(k0 + ty + i*8) * N + n0 + tx];
    __syncthreads();
    #pragma unroll
    for (int i = 0; i < 4; i++) {
        int n = n0 + ty + i*8;
        Th[(size_t)n * K + k0 + tx] = __float2half_rn(s[tx][ty + i*8]);
    }
}

// ---------------- RoPE cos/sin table ----------------
__global__ void rope_table_kernel() {
    int idx = blockIdx.x * blockDim.x + threadIdx.x;
    if (idx >= SEQ * NROT) return;
    int s = idx >> 6;
    int i = idx & 63;
    double invf = pow(10000.0, -(double)(2*i) / (double)HDIM);
    double ang = (double)s * invf;
    g_cos[idx] = (float)cos(ang);
    g_sin[idx] = (float)sin(ang);
}

// ---------------- RoPE apply, in place on fp32 ----------------
__global__ __launch_bounds__(256) void rope_apply_kernel(float* __restrict__ t, int nheads, int total) {
    int idx = blockIdx.x * blockDim.x + threadIdx.x;
    if (idx >= total) return;
    int i = idx & 63;
    int rest = idx >> 6;
    int s = (rest / nheads) & (SEQ - 1);
    float c  = g_cos[(s << 6) + i];
    float sn = g_sin[(s << 6) + i];
    float2* p = (float2*)(t + (size_t)rest * HDIM) + i;
    float2 v = *p;
    *p = make_float2(v.x*c - v.y*sn, v.x*sn + v.y*c);
}

// ================= mma.sync fp16 GEMM, 2-pass hi/lo on A =================
// C[M,N] = (Ah+Al)[M,K] * Bh^T[N,K], fp32 out. CTA 128x128, K-chunk 32, 4 stages.
#define GK       32
#define ROWB     80u
#define TILEP    (128u * ROWB)          // 10240 B
#define STAGEB   (3u * TILEP)           // Ah, Al, Bh
#define NSTAGE   4
#define GEMM_SMEM (NSTAGE * STAGEB)     // 122880

__global__ __launch_bounds__(256, 1) void hgemm_kernel(
        const __half* __restrict__ Ah, const __half* __restrict__ Al,
        const __half* __restrict__ Bh,
        float* __restrict__ C, int N, int Kd) {
    extern __shared__ char smem[];
    const uint32_t sb = smem_to_u32(smem);
    const int tid  = threadIdx.x;
    const int lane = tid & 31, wid = tid >> 5;
    const int bm = blockIdx.y * 128, bn = blockIdx.x * 128;
    const int wm = (wid & 3) * 32, wn = (wid >> 2) * 64;
    const int NCH = Kd / GK;

    const int lr = tid >> 2;
    const int colel = (tid & 3) * 8;
    const uint32_t so_base = (uint32_t)(tid & 3) * 16u;

    uint32_t aoff[2], boff[4];
    #pragma unroll
    for (int mi = 0; mi < 2; mi++)
        aoff[mi] = (uint32_t)(wm + mi*16 + (lane & 15)) * ROWB + ((uint32_t)(lane >> 4) << 4);
    #pragma unroll
    for (int f = 0; f < 4; f++) {
        int rb = wn + f*16 + (lane & 7) + ((lane >> 4) << 3);
        boff[f] = (uint32_t)rb * ROWB + (((uint32_t)(lane >> 3) & 1u) << 4);
    }

    float acc[2][8][4];
    #pragma unroll
    for (int mi = 0; mi < 2; mi++)
        #pragma unroll
        for (int ni = 0; ni < 8; ni++)
            #pragma unroll
            for (int c = 0; c < 4; c++) acc[mi][ni][c] = 0.f;

    auto load_chunk = [&](int stage, int k0) {
        uint32_t s0 = sb + (uint32_t)stage * STAGEB;
        #pragma unroll
        for (int h = 0; h < 2; h++) {
            int r = lr + h * 64;
            uint32_t so = (uint32_t)r * ROWB + so_base;
            size_t gaofs = (size_t)(bm + r) * Kd + k0 + colel;
            size_t gbofs = (size_t)(bn + r) * Kd + k0 + colel;
            cp_async16(s0 + so,             Ah + gaofs);
            cp_async16(s0 + TILEP + so,     Al + gaofs);
            cp_async16(s0 + 2u*TILEP + so,  Bh + gbofs);
        }
    };

    auto compute = [&](int stage) {
        uint32_t s0 = sb + (uint32_t)stage * STAGEB;
        #pragma unroll
        for (int ks = 0; ks < 2; ks++) {
            uint32_t ah[2][4], al[2][4], bh[4][4];
            #pragma unroll
            for (int mi = 0; mi < 2; mi++) {
                ldm_x4(ah[mi], s0 + aoff[mi] + ks*32);
                ldm_x4(al[mi], s0 + TILEP + aoff[mi] + ks*32);
            }
            #pragma unroll
            for (int f = 0; f < 4; f++)
                ldm_x4(bh[f], s0 + 2u*TILEP + boff[f] + ks*32);
            #pragma unroll
            for (int mi = 0; mi < 2; mi++)
                #pragma unroll
                for (int f = 0; f < 4; f++) {
                    mma16816(acc[mi][2*f],   ah[mi], &bh[f][0]);
                    mma16816(acc[mi][2*f+1], ah[mi], &bh[f][2]);
                    mma16816(acc[mi][2*f],   al[mi], &bh[f][0]);
                    mma16816(acc[mi][2*f+1], al[mi], &bh[f][2]);
                }
        }
    };

    load_chunk(0, 0);      CP_COMMIT();
    load_chunk(1, GK);     CP_COMMIT();
    load_chunk(2, 2*GK);   CP_COMMIT();

    for (int i = 0; i < NCH; i++) {
        if (i < NCH - 2)       CP_WAIT(2);
        else if (i == NCH - 2) CP_WAIT(1);
        else                   CP_WAIT(0);
        __syncthreads();
        if (i + 3 < NCH) { load_chunk((i + 3) % NSTAGE, (i + 3) * GK); CP_COMMIT(); }
        compute(i % NSTAGE);
    }

    #pragma unroll
    for (int mi = 0; mi < 2; mi++) {
        int row = bm + wm + mi*16 + (lane >> 2);
        #pragma unroll
        for (int ni = 0; ni < 8; ni++) {
            int col = bn + wn + ni*8 + (lane & 3)*2;
            float* p = C + (size_t)row * N + col;
            *(float2*)p           = make_float2(acc[mi][ni][0], acc[mi][ni][1]);
            *(float2*)(p + 8*N)   = make_float2(acc[mi][ni][2], acc[mi][ni][3]);
        }
    }
}

// ================= tensor-core flash attention (fp16 2-pass) =================
// CTA = (qtile 64, head, batch), 128 threads (4 warps), warp owns 16 q rows.
// smem tiles, all row-stride 136 halves (272 B):
//   Qh[64][128], Ql[64][128], Kh[64][128], Vs[64][128] (K/V natural [kv][d])
#define ATS   136            // halves per row
#define ATSB  272u           // bytes per row
#define AT_TILE (64*ATS*2)   // 17408 B
#define QH_OFF 0
#define QL_OFF AT_TILE
#define KH_OFF (2*AT_TILE)
#define VS_OFF (3*AT_TILE)
#define ATT_SMEM (4*AT_TILE) // 69632

__global__ __launch_bounds__(128, 2) void attn_kernel(const float* __restrict__ Q,
                                                      const float* __restrict__ K,
                                                      const float* __restrict__ V) {
    extern __shared__ char smem[];
    const uint32_t sb = smem_to_u32(smem);
    __half* Qh = (__half*)(smem + QH_OFF);
    __half* Ql = (__half*)(smem + QL_OFF);
    __half* Kh = (__half*)(smem + KH_OFF);
    __half* Vs = (__half*)(smem + VS_OFF);

    const int tid = threadIdx.x;
    const int lane = tid & 31, w = tid >> 5;
    const int qt = blockIdx.x, h = blockIdx.y, b = blockIdx.z;
    const int kh = h >> 2;
    const int qstart = qt * 64;
    const float scale = 0.08838834764831845f;

    // ---- load + scale + split Q tile ----
    for (int it = tid; it < 64*32; it += 128) {
        int r = it >> 5, c4 = it & 31;
        const float* qp = Q + (((size_t)b*SEQ + qstart + r)*NH + h)*HDIM + c4*4;
        float4 qv = *(const float4*)qp;
        qv.x *= scale; qv.y *= scale; qv.z *= scale; qv.w *= scale;
        __half hx = __float2half_rn(qv.x), hy = __float2half_rn(qv.y);
        __half hz = __float2half_rn(qv.z), hw = __float2half_rn(qv.w);
        int o = r*ATS + c4*4;
        *(__half2*)&Qh[o]   = __halves2half2(hx, hy);
        *(__half2*)&Qh[o+2] = __halves2half2(hz, hw);
        *(__half2*)&Ql[o]   = __halves2half2(__float2half_rn(qv.x - __half2float(hx)),
                                             __float2half_rn(qv.y - __half2float(hy)));
        *(__half2*)&Ql[o+2] = __halves2half2(__float2half_rn(qv.z - __half2float(hz)),
                                             __float2half_rn(qv.w - __half2float(hw)));
    }

    // fragment addresses (lane-dependent, tile-relative)
    const uint32_t a_off = (uint32_t)(w*16 + (lane & 15)) * ATSB + ((uint32_t)(lane >> 4) << 4);
    const uint32_t qh_ad = sb + QH_OFF + a_off;
    const uint32_t ql_ad = sb + QL_OFF + a_off;
    // K as B (non-trans): rows = kv(n)
    uint32_t kb_ad[4];
    #pragma unroll
    for (int f = 0; f < 4; f++)
        kb_ad[f] = sb + KH_OFF + (uint32_t)(f*16 + (lane & 7) + ((lane >> 4) << 3)) * ATSB
                 + (((uint32_t)(lane >> 3) & 1u) << 4);
    // V as B via trans: rows = kv(k)
    const uint32_t v_row = (uint32_t)((lane & 7) + (((lane >> 3) & 1) << 3));
    const uint32_t v_colsh = ((uint32_t)(lane >> 4) & 1u) << 4;

    const int qrow0 = qstart + w*16 + (lane >> 2);   // rows for c0,c1 (c2,c3 at +8)

    float oacc[16][4];
    #pragma unroll
    for (int t = 0; t < 16; t++)
        #pragma unroll
        for (int e = 0; e < 4; e++) oacc[t][e] = 0.f;
    float m0 = -3.0e38f, m1 = -3.0e38f, l0 = 0.f, l1 = 0.f;

    int kmin = qstart - WIN; if (kmin < 0) kmin = 0;
    const int kmax = qstart + 63;

    for (int k0 = kmin; k0 <= kmax; k0 += 64) {
        __syncthreads();   // prior-tile smem reads done
        // ---- load K, V tiles (natural layout, fp16) ----
        for (int it = tid; it < 64*32; it += 128) {
            int r = it >> 5, c4 = it & 31;
            size_t gofs = (((size_t)b*SEQ + k0 + r)*NKH + kh)*HDIM + c4*4;
            float4 kv4 = *(const float4*)(K + gofs);
            float4 vv4 = *(const float4*)(V + gofs);
            int o = r*ATS + c4*4;
            *(__half2*)&Kh[o]   = __floats2half2_rn(kv4.x, kv4.y);
            *(__half2*)&Kh[o+2] = __floats2half2_rn(kv4.z, kv4.w);
            *(__half2*)&Vs[o]   = __floats2half2_rn(vv4.x, vv4.y);
            *(__half2*)&Vs[o+2] = __floats2half2_rn(vv4.z, vv4.w);
        }
        __syncthreads();

        // ---- S = Q K^T (2-pass), fp32 frags ----
        float sacc[8][4];
        #pragma unroll
        for (int t = 0; t < 8; t++)
            #pragma unroll
            for (int e = 0; e < 4; e++) sacc[t][e] = 0.f;

        #pragma unroll
        for (int ks = 0; ks < 8; ks++) {
            uint32_t qa[4], qb[4];
            ldm_x4(qa, qh_ad + ks*32);
            ldm_x4(qb, ql_ad + ks*32);
            #pragma unroll
            for (int f = 0; f < 4; f++) {
                uint32_t kb[4];
                ldm_x4(kb, kb_ad[f] + ks*32);
                mma16816(sacc[2*f],   qa, &kb[0]);
                mma16816(sacc[2*f+1], qa, &kb[2]);
                mma16816(sacc[2*f],   qb, &kb[0]);
                mma16816(sacc[2*f+1], qb, &kb[2]);
            }
        }

        // ---- mask ----
        #pragma unroll
        for (int t = 0; t < 8; t++) {
            int kvb = k0 + t*8 + 2*(lane & 3);
            #pragma unroll
            for (int e = 0; e < 4; e++) {
                int qp = qrow0 + ((e >> 1) << 3);
                int dlt = qp - (kvb + (e & 1));
                if (dlt < 0 || dlt > WIN) sacc[t][e] = -3.0e38f;
            }
        }

        // ---- online softmax (rows qrow0, qrow0+8) ----
        float mt0 = -3.0e38f, mt1 = -3.0e38f;
        #pragma unroll
        for (int t = 0; t < 8; t++) {
            mt0 = fmaxf(mt0, fmaxf(sacc[t][0], sacc[t][1]));
            mt1 = fmaxf(mt1, fmaxf(sacc[t][2], sacc[t][3]));
        }
        mt0 = fmaxf(mt0, __shfl_xor_sync(0xffffffffu, mt0, 1));
        mt0 = fmaxf(mt0, __shfl_xor_sync(0xffffffffu, mt0, 2));
        mt1 = fmaxf(mt1, __shfl_xor_sync(0xffffffffu, mt1, 1));
        mt1 = fmaxf(mt1, __shfl_xor_sync(0xffffffffu, mt1, 2));
        float m0n = fmaxf(m0, mt0), m1n = fmaxf(m1, mt1);
        float al0 = __expf(m0 - m0n), al1 = __expf(m1 - m1n);
        m0 = m0n; m1 = m1n;
        float s0 = 0.f, s1 = 0.f;
        #pragma unroll
        for (int t = 0; t < 8; t++) {
            sacc[t][0] = __expf(sacc[t][0] - m0n);
            sacc[t][1] = __expf(sacc[t][1] - m0n);
            sacc[t][2] = __expf(sacc[t][2] - m1n);
            sacc[t][3] = __expf(sacc[t][3] - m1n);
            s0 += sacc[t][0] + sacc[t][1];
            s1 += sacc[t][2] + sacc[t][3];
        }
        s0 += __shfl_xor_sync(0xffffffffu, s0, 1);
        s0 += __shfl_xor_sync(0xffffffffu, s0, 2);
        s1 += __shfl_xor_sync(0xffffffffu, s1, 1);
        s1 += __shfl_xor_sync(0xffffffffu, s1, 2);
        l0 = l0 * al0 + s0;
        l1 = l1 * al1 + s1;
        #pragma unroll
        for (int t = 0; t < 16; t++) {
            oacc[t][0] *= al0; oacc[t][1] *= al0;
            oacc[t][2] *= al1; oacc[t][3] *= al1;
        }

        // ---- O += P V (2-pass on P) ----
        #pragma unroll
        for (int u = 0; u < 4; u++) {
            // build A-frags (P hi/lo) from S tiles 2u, 2u+1
            uint32_t aph[4], apl[4];
            #pragma unroll
            for (int half_t = 0; half_t < 2; half_t++) {
                int t = 2*u + half_t;
                __half h0 = __float2half_rn(sacc[t][0]);
                __half h1 = __float2half_rn(sacc[t][1]);
                __half h2 = __float2half_rn(sacc[t][2]);
                __half h3 = __float2half_rn(sacc[t][3]);
                aph[0 + 2*half_t] = pack_h2(h0, h1);
                aph[1 + 2*half_t] = pack_h2(h2, h3);
                apl[0 + 2*half_t] = pack_h2(__float2half_rn(sacc[t][0] - __half2float(h0)),
                                            __float2half_rn(sacc[t][1] - __half2float(h1)));
                apl[1 + 2*half_t] = pack_h2(__float2half_rn(sacc[t][2] - __half2float(h2)),
                                            __float2half_rn(sacc[t][3] - __half2float(h3)));
            }
            #pragma unroll
            for (int f2 = 0; f2 < 8; f2++) {
                uint32_t bv[4];
                ldm_x4_t(bv, sb + VS_OFF + (u*16 + v_row) * ATSB + (uint32_t)f2*32 + v_colsh);
                mma16816(oacc[2*f2],   aph, &bv[0]);
                mma16816(oacc[2*f2+1], aph, &bv[2]);
                mma16816(oacc[2*f2],   apl, &bv[0]);
                mma16816(oacc[2*f2+1], apl, &bv[2]);
            }
        }
    }

    // ---- epilogue: normalize, split to fp16 hi/lo, store ----
    float inv0 = 1.0f / l0, inv1 = 1.0f / l1;
    size_t base0 = (((size_t)b*SEQ + qrow0)*NH + h)*HDIM;
    size_t base1 = (((size_t)b*SEQ + qrow0 + 8)*NH + h)*HDIM;
    #pragma unroll
    for (int t = 0; t < 16; t++) {
        int d = t*8 + 2*(lane & 3);
        float o0 = oacc[t][0]*inv0, o1 = oacc[t][1]*inv0;
        float o2 = oacc[t][2]*inv1, o3 = oacc[t][3]*inv1;
        __half h0 = __float2half_rn(o0), h1 = __float2half_rn(o1);
        __half h2 = __float2half_rn(o2), h3 = __float2half_rn(o3);
        *(__half2*)(g_ao_hi + base0 + d) = __halves2half2(h0, h1);
        *(__half2*)(g_ao_hi + base1 + d) = __halves2half2(h2, h3);
        *(__half2*)(g_ao_lo + base0 + d) = __halves2half2(__float2half_rn(o0 - __half2float(h0)),
                                                          __float2half_rn(o1 - __half2float(h1)));
        *(__half2*)(g_ao_lo + base1 + d) = __halves2half2(__float2half_rn(o2 - __half2float(h2)),
                                                          __float2half_rn(o3 - __half2float(h3)));
    }
}

// ---------------- launcher ----------------
extern "C" void kernel_launch(void* const* d_in, const int* in_sizes, int n_in,
                              void* d_out, int out_size) {
    (void)in_sizes; (void)n_in; (void)out_size;
    const float* x    = (const float*)d_in[0];
    const float* ln_w = (const float*)d_in[1];
    const float* wq   = (const float*)d_in[2];
    const float* wk   = (const float*)d_in[3];
    const float* wv   = (const float*)d_in[4];
    const float* wo   = (const float*)d_in[5];
    float* out = (float*)d_out;

    float *p_q, *p_k, *p_v;
    __half *p_xnh, *p_xnl, *p_aoh, *p_aol, *p_wq, *p_wk, *p_wv, *p_wo;
    cudaGetSymbolAddress((void**)&p_q,   g_q);
    cudaGetSymbolAddress((void**)&p_k,   g_k);
    cudaGetSymbolAddress((void**)&p_v,   g_v);
    cudaGetSymbolAddress((void**)&p_xnh, g_xn_hi);
    cudaGetSymbolAddress((void**)&p_xnl, g_xn_lo);
    cudaGetSymbolAddress((void**)&p_aoh, g_ao_hi);
    cudaGetSymbolAddress((void**)&p_aol, g_ao_lo);
    cudaGetSymbolAddress((void**)&p_wq,  g_wqT);
    cudaGetSymbolAddress((void**)&p_wk,  g_wkT);
    cudaGetSymbolAddress((void**)&p_wv,  g_wvT);
    cudaGetSymbolAddress((void**)&p_wo,  g_woT);

    cudaFuncSetAttribute(attn_kernel,  cudaFuncAttributeMaxDynamicSharedMemorySize, ATT_SMEM);
    cudaFuncSetAttribute(hgemm_kernel, cudaFuncAttributeMaxDynamicSharedMemorySize, GEMM_SMEM);

    rmsnorm_kernel<<<MTOT, 256>>>(x, ln_w);
    rope_table_kernel<<<(SEQ*NROT + 255)/256, 256>>>();

    wtrans_kernel<<<dim3(DM/32, DM/32), 256>>>(wq, p_wq, DM, DM);
    wtrans_kernel<<<dim3((NKH*HDIM)/32, DM/32), 256>>>(wk, p_wk, DM, NKH*HDIM);
    wtrans_kernel<<<dim3((NKH*HDIM)/32, DM/32), 256>>>(wv, p_wv, DM, NKH*HDIM);
    wtrans_kernel<<<dim3(DM/32, DM/32), 256>>>(wo, p_wo, DM, DM);

    hgemm_kernel<<<dim3(DM/128,         MTOT/128), 256, GEMM_SMEM>>>(p_xnh, p_xnl, p_wq, p_q, DM,       DM);
    hgemm_kernel<<<dim3((NKH*HDIM)/128, MTOT/128), 256, GEMM_SMEM>>>(p_xnh, p_xnl, p_wk, p_k, NKH*HDIM, DM);
    hgemm_kernel<<<dim3((NKH*HDIM)/128, MTOT/128), 256, GEMM_SMEM>>>(p_xnh, p_xnl, p_wv, p_v, NKH*HDIM, DM);

    {
        int tq = MTOT*NH*NROT;
        rope_apply_kernel<<<(tq + 255)/256, 256>>>(p_q, NH, tq);
        int tk = MTOT*NKH*NROT;
        rope_apply_kernel<<<(tk + 255)/256, 256>>>(p_k, NKH, tk);
    }

    attn_kernel<<<dim3(SEQ/64, NH, BC), 128, ATT_SMEM>>>(p_q, p_k, p_v);

    hgemm_kernel<<<dim3(DM/128, MTOT/128), 256, GEMM_SMEM>>>(p_aoh, p_aol, p_wo, out, DM, DM);
}

// round 7
// speedup vs baseline: 1.1636x; 1.1636x over previous
#include <cuda_runtime.h>
#include <cuda_fp16.h>
#include <math.h>
#include <stdint.h>

#define BC    2
#define SEQ   4096
#define NH    16
#define NKH   4
#define HDIM  128
#define DM    2048
#define WIN   512
#define NROT  64
#define MTOT  (BC*SEQ)   // 8192

// ---------------- scratch (device globals) ----------------
__device__ float g_q  [MTOT*NH*HDIM];
__device__ float g_k  [MTOT*NKH*HDIM];
__device__ float g_v  [MTOT*NKH*HDIM];
__device__ float g_cos[SEQ*NROT];
__device__ float g_sin[SEQ*NROT];

__device__ __half g_xn_hi[MTOT*DM];
__device__ __half g_xn_lo[MTOT*DM];
__device__ __half g_ao_hi[MTOT*NH*HDIM];
__device__ __half g_wqT[DM*DM];
__device__ __half g_wkT[(NKH*HDIM)*DM];
__device__ __half g_wvT[(NKH*HDIM)*DM];
__device__ __half g_woT[DM*DM];

// ================= low-level helpers =================
__device__ __forceinline__ uint32_t smem_to_u32(const void* p) {
    uint32_t a;
    asm("{ .reg .u64 t; cvta.to.shared.u64 t, %1; cvt.u32.u64 %0, t; }" : "=r"(a) : "l"(p));
    return a;
}
__device__ __forceinline__ void cp_async16(uint32_t dst, const void* src) {
    asm volatile("cp.async.cg.shared.global [%0], [%1], 16;" :: "r"(dst), "l"(src) : "memory");
}
#define CP_COMMIT() asm volatile("cp.async.commit_group;" ::: "memory")
#define CP_WAIT(n)  asm volatile("cp.async.wait_group %0;" :: "n"(n) : "memory")

__device__ __forceinline__ void ldm_x4(uint32_t* r, uint32_t addr) {
    asm volatile("ldmatrix.sync.aligned.m8n8.x4.shared.b16 {%0,%1,%2,%3}, [%4];"
        : "=r"(r[0]), "=r"(r[1]), "=r"(r[2]), "=r"(r[3]) : "r"(addr));
}
__device__ __forceinline__ void ldm_x4_t(uint32_t* r, uint32_t addr) {
    asm volatile("ldmatrix.sync.aligned.m8n8.x4.trans.shared.b16 {%0,%1,%2,%3}, [%4];"
        : "=r"(r[0]), "=r"(r[1]), "=r"(r[2]), "=r"(r[3]) : "r"(addr));
}
__device__ __forceinline__ void mma16816(float* d, const uint32_t* a, const uint32_t* b) {
    asm volatile("mma.sync.aligned.m16n8k16.row.col.f32.f16.f16.f32 "
        "{%0,%1,%2,%3}, {%4,%5,%6,%7}, {%8,%9}, {%0,%1,%2,%3};"
        : "+f"(d[0]), "+f"(d[1]), "+f"(d[2]), "+f"(d[3])
        : "r"(a[0]), "r"(a[1]), "r"(a[2]), "r"(a[3]), "r"(b[0]), "r"(b[1]));
}
__device__ __forceinline__ uint32_t pack_h2(__half a, __half b) {
    __half2 h = __halves2half2(a, b);
    return *(uint32_t*)&h;
}
__device__ __forceinline__ void split_store_h(__half2* oh, __half2* ol, int idx2, float a, float b) {
    __half ah = __float2half_rn(a), bh = __float2half_rn(b);
    oh[idx2] = __halves2half2(ah, bh);
    ol[idx2] = __halves2half2(__float2half_rn(a - __half2float(ah)),
                              __float2half_rn(b - __half2float(bh)));
}

// ---------------- RMSNorm ----------------
__global__ __launch_bounds__(256) void rmsnorm_kernel(const float* __restrict__ x,
                                                      const float* __restrict__ w) {
    int row = blockIdx.x;
    const float4* xr = (const float4*)(x + (size_t)row * DM);
    float4 v0 = xr[threadIdx.x];
    float4 v1 = xr[threadIdx.x + 256];
    float ss = v0.x*v0.x + v0.y*v0.y + v0.z*v0.z + v0.w*v0.w
             + v1.x*v1.x + v1.y*v1.y + v1.z*v1.z + v1.w*v1.w;
    #pragma unroll
    for (int off = 16; off > 0; off >>= 1) ss += __shfl_xor_sync(0xffffffffu, ss, off);
    __shared__ float red[8];
    if ((threadIdx.x & 31) == 0) red[threadIdx.x >> 5] = ss;
    __syncthreads();
    float tot = 0.f;
    #pragma unroll
    for (int i = 0; i < 8; i++) tot += red[i];
    float scl = rsqrtf(tot * (1.0f/DM) + 1e-6f);
    const float4* wr = (const float4*)w;
    float4 w0 = wr[threadIdx.x];
    float4 w1 = wr[threadIdx.x + 256];
    __half2* oh = (__half2*)(g_xn_hi + (size_t)row * DM);
    __half2* ol = (__half2*)(g_xn_lo + (size_t)row * DM);
    split_store_h(oh, ol, 2*threadIdx.x,   v0.x*scl*w0.x, v0.y*scl*w0.y);
    split_store_h(oh, ol, 2*threadIdx.x+1, v0.z*scl*w0.z, v0.w*scl*w0.w);
    split_store_h(oh, ol, 2*(threadIdx.x+256),   v1.x*scl*w1.x, v1.y*scl*w1.y);
    split_store_h(oh, ol, 2*(threadIdx.x+256)+1, v1.z*scl*w1.z, v1.w*scl*w1.w);
}

// ---------------- weight transpose to fp16 ----------------
__global__ __launch_bounds__(256) void wtrans_kernel(const float* __restrict__ W,
                                                     __half* __restrict__ Th,
                                                     int K, int N) {
    __shared__ float s[32][33];
    int tx = threadIdx.x & 31, ty = threadIdx.x >> 5;
    int n0 = blockIdx.x * 32, k0 = blockIdx.y * 32;
    #pragma unroll
    for (int i = 0; i < 4; i++)
        s[ty + i*8][tx] = W[(size_t)(k0 + ty + i*8) * N + n0 + tx];
    __syncthreads();
    #pragma unroll
    for (int i = 0; i < 4; i++) {
        int n = n0 + ty + i*8;
        Th[(size_t)n * K + k0 + tx] = __float2half_rn(s[tx][ty + i*8]);
    }
}

// ---------------- RoPE cos/sin table ----------------
__global__ void rope_table_kernel() {
    int idx = blockIdx.x * blockDim.x + threadIdx.x;
    if (idx >= SEQ * NROT) return;
    int s = idx >> 6;
    int i = idx & 63;
    double invf = pow(10000.0, -(double)(2*i) / (double)HDIM);
    double ang = (double)s * invf;
    g_cos[idx] = (float)cos(ang);
    g_sin[idx] = (float)sin(ang);
}

// ================= mma.sync fp16 GEMM =================
// C[M,N] = (Ah [+Al])[M,K] * Bh^T[N,K], fp32 out. CTA 128x128, K-chunk 32, 4 stages.
// TP: 2-pass hi/lo on A.  RNH>0: apply RoPE to output pairs (RNH = heads in tensor).
#define GK       32
#define ROWB     80u
#define TILEP    (128u * ROWB)          // 10240 B
#define NSTAGE   4
#define GEMM_SMEM_MAX (NSTAGE * 3u * TILEP)   // 122880 (2-pass variant)

template<bool TP, int RNH>
__global__ __launch_bounds__(256, 1) void hgemm_kernel(
        const __half* __restrict__ Ah, const __half* __restrict__ Al,
        const __half* __restrict__ Bh,
        float* __restrict__ C, int N, int Kd) {
    constexpr uint32_t NT = TP ? 3u : 2u;     // tiles per stage
    constexpr uint32_t STAGEB = NT * TILEP;
    constexpr uint32_t BOFFS = (TP ? 2u : 1u) * TILEP;
    extern __shared__ char smem[];
    const uint32_t sb = smem_to_u32(smem);
    const int tid  = threadIdx.x;
    const int lane = tid & 31, wid = tid >> 5;
    const int bm = blockIdx.y * 128, bn = blockIdx.x * 128;
    const int wm = (wid & 3) * 32, wn = (wid >> 2) * 64;
    const int NCH = Kd / GK;

    const int lr = tid >> 2;
    const int colel = (tid & 3) * 8;
    const uint32_t so_base = (uint32_t)(tid & 3) * 16u;

    uint32_t aoff[2], boff[4];
    #pragma unroll
    for (int mi = 0; mi < 2; mi++)
        aoff[mi] = (uint32_t)(wm + mi*16 + (lane & 15)) * ROWB + ((uint32_t)(lane >> 4) << 4);
    #pragma unroll
    for (int f = 0; f < 4; f++) {
        int rb = wn + f*16 + (lane & 7) + ((lane >> 4) << 3);
        boff[f] = (uint32_t)rb * ROWB + (((uint32_t)(lane >> 3) & 1u) << 4);
    }

    float acc[2][8][4];
    #pragma unroll
    for (int mi = 0; mi < 2; mi++)
        #pragma unroll
        for (int ni = 0; ni < 8; ni++)
            #pragma unroll
            for (int c = 0; c < 4; c++) acc[mi][ni][c] = 0.f;

    auto load_chunk = [&](int stage, int k0) {
        uint32_t s0 = sb + (uint32_t)stage * STAGEB;
        #pragma unroll
        for (int h = 0; h < 2; h++) {
            int r = lr + h * 64;
            uint32_t so = (uint32_t)r * ROWB + so_base;
            size_t gaofs = (size_t)(bm + r) * Kd + k0 + colel;
            size_t gbofs = (size_t)(bn + r) * Kd + k0 + colel;
            cp_async16(s0 + so, Ah + gaofs);
            if (TP) cp_async16(s0 + TILEP + so, Al + gaofs);
            cp_async16(s0 + BOFFS + so, Bh + gbofs);
        }
    };

    auto compute = [&](int stage) {
        uint32_t s0 = sb + (uint32_t)stage * STAGEB;
        #pragma unroll
        for (int ks = 0; ks < 2; ks++) {
            uint32_t ah[2][4], al[2][4], bh[4][4];
            #pragma unroll
            for (int mi = 0; mi < 2; mi++) {
                ldm_x4(ah[mi], s0 + aoff[mi] + ks*32);
                if (TP) ldm_x4(al[mi], s0 + TILEP + aoff[mi] + ks*32);
            }
            #pragma unroll
            for (int f = 0; f < 4; f++)
                ldm_x4(bh[f], s0 + BOFFS + boff[f] + ks*32);
            #pragma unroll
            for (int mi = 0; mi < 2; mi++)
                #pragma unroll
                for (int f = 0; f < 4; f++) {
                    mma16816(acc[mi][2*f],   ah[mi], &bh[f][0]);
                    mma16816(acc[mi][2*f+1], ah[mi], &bh[f][2]);
                    if (TP) {
                        mma16816(acc[mi][2*f],   al[mi], &bh[f][0]);
                        mma16816(acc[mi][2*f+1], al[mi], &bh[f][2]);
                    }
                }
        }
    };

    load_chunk(0, 0);      CP_COMMIT();
    load_chunk(1, GK);     CP_COMMIT();
    load_chunk(2, 2*GK);   CP_COMMIT();

    for (int i = 0; i < NCH; i++) {
        if (i < NCH - 2)       CP_WAIT(2);
        else if (i == NCH - 2) CP_WAIT(1);
        else                   CP_WAIT(0);
        __syncthreads();
        if (i + 3 < NCH) { load_chunk((i + 3) % NSTAGE, (i + 3) * GK); CP_COMMIT(); }
        compute(i % NSTAGE);
    }

    #pragma unroll
    for (int mi = 0; mi < 2; mi++) {
        int row = bm + wm + mi*16 + (lane >> 2);
        #pragma unroll
        for (int ni = 0; ni < 8; ni++) {
            int col = bn + wn + ni*8 + (lane & 3)*2;
            if (RNH > 0) {
                // rope: (c0,c1) = (even,odd) at row; (c2,c3) at row+8
                int i2 = (col & 127) >> 1;
                int s0i = ((row & (SEQ-1)) << 6) + i2;
                int s1i = (((row + 8) & (SEQ-1)) << 6) + i2;
                float c0 = g_cos[s0i], sn0 = g_sin[s0i];
                float c1 = g_cos[s1i], sn1 = g_sin[s1i];
                float e0 = acc[mi][ni][0], o0 = acc[mi][ni][1];
                float e1 = acc[mi][ni][2], o1 = acc[mi][ni][3];
                acc[mi][ni][0] = e0*c0 - o0*sn0;
                acc[mi][ni][1] = e0*sn0 + o0*c0;
                acc[mi][ni][2] = e1*c1 - o1*sn1;
                acc[mi][ni][3] = e1*sn1 + o1*c1;
            }
            float* p = C + (size_t)row * N + col;
            *(float2*)p         = make_float2(acc[mi][ni][0], acc[mi][ni][1]);
            *(float2*)(p + 8*N) = make_float2(acc[mi][ni][2], acc[mi][ni][3]);
        }
    }
}

// ================= tensor-core flash attention (fp16 2-pass Q/P) =================
#define ATS   136
#define ATSB  272u
#define AT_TILE (64*ATS*2)
#define QH_OFF 0
#define QL_OFF AT_TILE
#define KH_OFF (2*AT_TILE)
#define VS_OFF (3*AT_TILE)
#define ATT_SMEM (4*AT_TILE)

__global__ __launch_bounds__(128, 2) void attn_kernel(const float* __restrict__ Q,
                                                      const float* __restrict__ K,
                                                      const float* __restrict__ V) {
    extern __shared__ char smem[];
    const uint32_t sb = smem_to_u32(smem);
    __half* Qh = (__half*)(smem + QH_OFF);
    __half* Ql = (__half*)(smem + QL_OFF);
    __half* Kh = (__half*)(smem + KH_OFF);
    __half* Vs = (__half*)(smem + VS_OFF);

    const int tid = threadIdx.x;
    const int lane = tid & 31, w = tid >> 5;
    const int qt = blockIdx.x, h = blockIdx.y, b = blockIdx.z;
    const int kh = h >> 2;
    const int qstart = qt * 64;
    const float scale = 0.08838834764831845f;

    for (int it = tid; it < 64*32; it += 128) {
        int r = it >> 5, c4 = it & 31;
        const float* qp = Q + (((size_t)b*SEQ + qstart + r)*NH + h)*HDIM + c4*4;
        float4 qv = *(const float4*)qp;
        qv.x *= scale; qv.y *= scale; qv.z *= scale; qv.w *= scale;
        __half hx = __float2half_rn(qv.x), hy = __float2half_rn(qv.y);
        __half hz = __float2half_rn(qv.z), hw = __float2half_rn(qv.w);
        int o = r*ATS + c4*4;
        *(__half2*)&Qh[o]   = __halves2half2(hx, hy);
        *(__half2*)&Qh[o+2] = __halves2half2(hz, hw);
        *(__half2*)&Ql[o]   = __halves2half2(__float2half_rn(qv.x - __half2float(hx)),
                                             __float2half_rn(qv.y - __half2float(hy)));
        *(__half2*)&Ql[o+2] = __halves2half2(__float2half_rn(qv.z - __half2float(hz)),
                                             __float2half_rn(qv.w - __half2float(hw)));
    }

    const uint32_t a_off = (uint32_t)(w*16 + (lane & 15)) * ATSB + ((uint32_t)(lane >> 4) << 4);
    const uint32_t qh_ad = sb + QH_OFF + a_off;
    const uint32_t ql_ad = sb + QL_OFF + a_off;
    uint32_t kb_ad[4];
    #pragma unroll
    for (int f = 0; f < 4; f++)
        kb_ad[f] = sb + KH_OFF + (uint32_t)(f*16 + (lane & 7) + ((lane >> 4) << 3)) * ATSB
                 + (((uint32_t)(lane >> 3) & 1u) << 4);
    const uint32_t v_row = (uint32_t)((lane & 7) + (((lane >> 3) & 1) << 3));
    const uint32_t v_colsh = ((uint32_t)(lane >> 4) & 1u) << 4;

    const int qrow0 = qstart + w*16 + (lane >> 2);

    float oacc[16][4];
    #pragma unroll
    for (int t = 0; t < 16; t++)
        #pragma unroll
        for (int e = 0; e < 4; e++) oacc[t][e] = 0.f;
    float m0 = -3.0e38f, m1 = -3.0e38f, l0 = 0.f, l1 = 0.f;

    int kmin = qstart - WIN; if (kmin < 0) kmin = 0;
    const int kmax = qstart + 63;

    for (int k0 = kmin; k0 <= kmax; k0 += 64) {
        __syncthreads();
        for (int it = tid; it < 64*32; it += 128) {
            int r = it >> 5, c4 = it & 31;
            size_t gofs = (((size_t)b*SEQ + k0 + r)*NKH + kh)*HDIM + c4*4;
            float4 kv4 = *(const float4*)(K + gofs);
            float4 vv4 = *(const float4*)(V + gofs);
            int o = r*ATS + c4*4;
            *(__half2*)&Kh[o]   = __floats2half2_rn(kv4.x, kv4.y);
            *(__half2*)&Kh[o+2] = __floats2half2_rn(kv4.z, kv4.w);
            *(__half2*)&Vs[o]   = __floats2half2_rn(vv4.x, vv4.y);
            *(__half2*)&Vs[o+2] = __floats2half2_rn(vv4.z, vv4.w);
        }
        __syncthreads();

        float sacc[8][4];
        #pragma unroll
        for (int t = 0; t < 8; t++)
            #pragma unroll
            for (int e = 0; e < 4; e++) sacc[t][e] = 0.f;

        #pragma unroll
        for (int ks = 0; ks < 8; ks++) {
            uint32_t qa[4], qb[4];
            ldm_x4(qa, qh_ad + ks*32);
            ldm_x4(qb, ql_ad + ks*32);
            #pragma unroll
            for (int f = 0; f < 4; f++) {
                uint32_t kb[4];
                ldm_x4(kb, kb_ad[f] + ks*32);
                mma16816(sacc[2*f],   qa, &kb[0]);
                mma16816(sacc[2*f+1], qa, &kb[2]);
                mma16816(sacc[2*f],   qb, &kb[0]);
                mma16816(sacc[2*f+1], qb, &kb[2]);
            }
        }

        #pragma unroll
        for (int t = 0; t < 8; t++) {
            int kvb = k0 + t*8 + 2*(lane & 3);
            #pragma unroll
            for (int e = 0; e < 4; e++) {
                int qp = qrow0 + ((e >> 1) << 3);
                int dlt = qp - (kvb + (e & 1));
                if (dlt < 0 || dlt > WIN) sacc[t][e] = -3.0e38f;
            }
        }

        float mt0 = -3.0e38f, mt1 = -3.0e38f;
        #pragma unroll
        for (int t = 0; t < 8; t++) {
            mt0 = fmaxf(mt0, fmaxf(sacc[t][0], sacc[t][1]));
            mt1 = fmaxf(mt1, fmaxf(sacc[t][2], sacc[t][3]));
        }
        mt0 = fmaxf(mt0, __shfl_xor_sync(0xffffffffu, mt0, 1));
        mt0 = fmaxf(mt0, __shfl_xor_sync(0xffffffffu, mt0, 2));
        mt1 = fmaxf(mt1, __shfl_xor_sync(0xffffffffu, mt1, 1));
        mt1 = fmaxf(mt1, __shfl_xor_sync(0xffffffffu, mt1, 2));
        float m0n = fmaxf(m0, mt0), m1n = fmaxf(m1, mt1);
        float al0 = __expf(m0 - m0n), al1 = __expf(m1 - m1n);
        m0 = m0n; m1 = m1n;
        float s0 = 0.f, s1 = 0.f;
        #pragma unroll
        for (int t = 0; t < 8; t++) {
            sacc[t][0] = __expf(sacc[t][0] - m0n);
            sacc[t][1] = __expf(sacc[t][1] - m0n);
            sacc[t][2] = __expf(sacc[t][2] - m1n);
            sacc[t][3] = __expf(sacc[t][3] - m1n);
            s0 += sacc[t][0] + sacc[t][1];
            s1 += sacc[t][2] + sacc[t][3];
        }
        s0 += __shfl_xor_sync(0xffffffffu, s0, 1);
        s0 += __shfl_xor_sync(0xffffffffu, s0, 2);
        s1 += __shfl_xor_sync(0xffffffffu, s1, 1);
        s1 += __shfl_xor_sync(0xffffffffu, s1, 2);
        l0 = l0 * al0 + s0;
        l1 = l1 * al1 + s1;
        #pragma unroll
        for (int t = 0; t < 16; t++) {
            oacc[t][0] *= al0; oacc[t][1] *= al0;
            oacc[t][2] *= al1; oacc[t][3] *= al1;
        }

        #pragma unroll
        for (int u = 0; u < 4; u++) {
            uint32_t aph[4], apl[4];
            #pragma unroll
            for (int half_t = 0; half_t < 2; half_t++) {
                int t = 2*u + half_t;
                __half h0 = __float2half_rn(sacc[t][0]);
                __half h1 = __float2half_rn(sacc[t][1]);
                __half h2 = __float2half_rn(sacc[t][2]);
                __half h3 = __float2half_rn(sacc[t][3]);
                aph[0 + 2*half_t] = pack_h2(h0, h1);
                aph[1 + 2*half_t] = pack_h2(h2, h3);
                apl[0 + 2*half_t] = pack_h2(__float2half_rn(sacc[t][0] - __half2float(h0)),
                                            __float2half_rn(sacc[t][1] - __half2float(h1)));
                apl[1 + 2*half_t] = pack_h2(__float2half_rn(sacc[t][2] - __half2float(h2)),
                                            __float2half_rn(sacc[t][3] - __half2float(h3)));
            }
            #pragma unroll
            for (int f2 = 0; f2 < 8; f2++) {
                uint32_t bv[4];
                ldm_x4_t(bv, sb + VS_OFF + (u*16 + v_row) * ATSB + (uint32_t)f2*32 + v_colsh);
                mma16816(oacc[2*f2],   aph, &bv[0]);
                mma16816(oacc[2*f2+1], aph, &bv[2]);
                mma16816(oacc[2*f2],   apl, &bv[0]);
                mma16816(oacc[2*f2+1], apl, &bv[2]);
            }
        }
    }

    // epilogue: normalize, store fp16 (hi only — wo GEMM is 1-pass)
    float inv0 = 1.0f / l0, inv1 = 1.0f / l1;
    size_t base0 = (((size_t)b*SEQ + qrow0)*NH + h)*HDIM;
    size_t base1 = (((size_t)b*SEQ + qrow0 + 8)*NH + h)*HDIM;
    #pragma unroll
    for (int t = 0; t < 16; t++) {
        int d = t*8 + 2*(lane & 3);
        *(__half2*)(g_ao_hi + base0 + d) =
            __floats2half2_rn(oacc[t][0]*inv0, oacc[t][1]*inv0);
        *(__half2*)(g_ao_hi + base1 + d) =
            __floats2half2_rn(oacc[t][2]*inv1, oacc[t][3]*inv1);
    }
}

// ---------------- launcher ----------------
extern "C" void kernel_launch(void* const* d_in, const int* in_sizes, int n_in,
                              void* d_out, int out_size) {
    (void)in_sizes; (void)n_in; (void)out_size;
    const float* x    = (const float*)d_in[0];
    const float* ln_w = (const float*)d_in[1];
    const float* wq   = (const float*)d_in[2];
    const float* wk   = (const float*)d_in[3];
    const float* wv   = (const float*)d_in[4];
    const float* wo   = (const float*)d_in[5];
    float* out = (float*)d_out;

    float *p_q, *p_k, *p_v;
    __half *p_xnh, *p_xnl, *p_aoh, *p_wq, *p_wk, *p_wv, *p_wo;
    cudaGetSymbolAddress((void**)&p_q,   g_q);
    cudaGetSymbolAddress((void**)&p_k,   g_k);
    cudaGetSymbolAddress((void**)&p_v,   g_v);
    cudaGetSymbolAddress((void**)&p_xnh, g_xn_hi);
    cudaGetSymbolAddress((void**)&p_xnl, g_xn_lo);
    cudaGetSymbolAddress((void**)&p_aoh, g_ao_hi);
    cudaGetSymbolAddress((void**)&p_wq,  g_wqT);
    cudaGetSymbolAddress((void**)&p_wk,  g_wkT);
    cudaGetSymbolAddress((void**)&p_wv,  g_wvT);
    cudaGetSymbolAddress((void**)&p_wo,  g_woT);

    cudaFuncSetAttribute(attn_kernel, cudaFuncAttributeMaxDynamicSharedMemorySize, ATT_SMEM);
    cudaFuncSetAttribute(hgemm_kernel<true,16>, cudaFuncAttributeMaxDynamicSharedMemorySize, GEMM_SMEM_MAX);
    cudaFuncSetAttribute(hgemm_kernel<true,4>,  cudaFuncAttributeMaxDynamicSharedMemorySize, GEMM_SMEM_MAX);
    cudaFuncSetAttribute(hgemm_kernel<false,0>, cudaFuncAttributeMaxDynamicSharedMemorySize, GEMM_SMEM_MAX);

    const uint32_t SM2P = NSTAGE * 3u * TILEP;   // 2-pass stages
    const uint32_t SM1P = NSTAGE * 2u * TILEP;   // 1-pass stages

    // launch order arranged so launch #6 (0-based idx 5, ncu -s 5 -c 1) = hgemm q
    rmsnorm_kernel<<<MTOT, 256>>>(x, ln_w);                               // 1
    rope_table_kernel<<<(SEQ*NROT + 255)/256, 256>>>();                   // 2
    wtrans_kernel<<<dim3(DM/32, DM/32), 256>>>(wq, p_wq, DM, DM);         // 3
    wtrans_kernel<<<dim3((NKH*HDIM)/32, DM/32), 256>>>(wk, p_wk, DM, NKH*HDIM); // 4
    wtrans_kernel<<<dim3((NKH*HDIM)/32, DM/32), 256>>>(wv, p_wv, DM, NKH*HDIM); // 5
    hgemm_kernel<true,16><<<dim3(DM/128, MTOT/128), 256, SM2P>>>(p_xnh, p_xnl, p_wq, p_q, DM, DM);  // 6 <- profiled
    hgemm_kernel<true,4><<<dim3((NKH*HDIM)/128, MTOT/128), 256, SM2P>>>(p_xnh, p_xnl, p_wk, p_k, NKH*HDIM, DM);
    hgemm_kernel<false,0><<<dim3((NKH*HDIM)/128, MTOT/128), 256, SM1P>>>(p_xnh, nullptr, p_wv, p_v, NKH*HDIM, DM);

    attn_kernel<<<dim3(SEQ/64, NH, BC), 128, ATT_SMEM>>>(p_q, p_k, p_v);

    wtrans_kernel<<<dim3(DM/32, DM/32), 256>>>(wo, p_wo, DM, DM);
    hgemm_kernel<false,0><<<dim3(DM/128, MTOT/128), 256, SM1P>>>(p_aoh, nullptr, p_wo, out, DM, DM);
}

// round 10
// speedup vs baseline: 2.0562x; 1.7671x over previous
#include <cuda_runtime.h>
#include <cuda_fp16.h>
#include <math.h>
#include <stdint.h>

#define BC    2
#define SEQ   4096
#define NH    16
#define NKH   4
#define HDIM  128
#define DM    2048
#define WIN   512
#define NROT  64
#define MTOT  (BC*SEQ)   // 8192

// ---------------- scratch (device globals) ----------------
__device__ __half g_q  [MTOT*NH*HDIM];    // fp16, rope+scale applied
__device__ __half g_k  [MTOT*NKH*HDIM];   // fp16, rope applied
__device__ __half g_v  [MTOT*NKH*HDIM];   // fp16
__device__ float  g_cos[SEQ*NROT];
__device__ float  g_sin[SEQ*NROT];
__device__ __half g_xn [MTOT*DM];
__device__ __half g_ao [MTOT*NH*HDIM];
__device__ __half g_wqT[DM*DM];
__device__ __half g_wkT[(NKH*HDIM)*DM];
__device__ __half g_wvT[(NKH*HDIM)*DM];
__device__ __half g_woT[DM*DM];

// ================= low-level helpers =================
__device__ __forceinline__ uint32_t smem_to_u32(const void* p) {
    uint32_t a;
    asm("{ .reg .u64 t; cvta.to.shared.u64 t, %1; cvt.u32.u64 %0, t; }" : "=r"(a) : "l"(p));
    return a;
}
__device__ __forceinline__ void cp_async16(uint32_t dst, const void* src) {
    asm volatile("cp.async.cg.shared.global [%0], [%1], 16;" :: "r"(dst), "l"(src) : "memory");
}
#define CP_COMMIT() asm volatile("cp.async.commit_group;" ::: "memory")
#define CP_WAIT(n)  asm volatile("cp.async.wait_group %0;" :: "n"(n) : "memory")

__device__ __forceinline__ void ldm_x4(uint32_t* r, uint32_t addr) {
    asm volatile("ldmatrix.sync.aligned.m8n8.x4.shared.b16 {%0,%1,%2,%3}, [%4];"
        : "=r"(r[0]), "=r"(r[1]), "=r"(r[2]), "=r"(r[3]) : "r"(addr));
}
__device__ __forceinline__ void ldm_x4_t(uint32_t* r, uint32_t addr) {
    asm volatile("ldmatrix.sync.aligned.m8n8.x4.trans.shared.b16 {%0,%1,%2,%3}, [%4];"
        : "=r"(r[0]), "=r"(r[1]), "=r"(r[2]), "=r"(r[3]) : "r"(addr));
}
__device__ __forceinline__ void mma16816(float* d, const uint32_t* a, const uint32_t* b) {
    asm volatile("mma.sync.aligned.m16n8k16.row.col.f32.f16.f16.f32 "
        "{%0,%1,%2,%3}, {%4,%5,%6,%7}, {%8,%9}, {%0,%1,%2,%3};"
        : "+f"(d[0]), "+f"(d[1]), "+f"(d[2]), "+f"(d[3])
        : "r"(a[0]), "r"(a[1]), "r"(a[2]), "r"(a[3]), "r"(b[0]), "r"(b[1]));
}
__device__ __forceinline__ uint32_t pack_h2(__half a, __half b) {
    __half2 h = __halves2half2(a, b);
    return *(uint32_t*)&h;
}

// ---------------- RMSNorm: fp16 out (hi only) ----------------
__global__ __launch_bounds__(256) void rmsnorm_kernel(const float* __restrict__ x,
                                                      const float* __restrict__ w) {
    int row = blockIdx.x;
    const float4* xr = (const float4*)(x + (size_t)row * DM);
    float4 v0 = xr[threadIdx.x];
    float4 v1 = xr[threadIdx.x + 256];
    float ss = v0.x*v0.x + v0.y*v0.y + v0.z*v0.z + v0.w*v0.w
             + v1.x*v1.x + v1.y*v1.y + v1.z*v1.z + v1.w*v1.w;
    #pragma unroll
    for (int off = 16; off > 0; off >>= 1) ss += __shfl_xor_sync(0xffffffffu, ss, off);
    __shared__ float red[8];
    if ((threadIdx.x & 31) == 0) red[threadIdx.x >> 5] = ss;
    __syncthreads();
    float tot = 0.f;
    #pragma unroll
    for (int i = 0; i < 8; i++) tot += red[i];
    float scl = rsqrtf(tot * (1.0f/DM) + 1e-6f);
    const float4* wr = (const float4*)w;
    float4 w0 = wr[threadIdx.x];
    float4 w1 = wr[threadIdx.x + 256];
    __half2* oh = (__half2*)(g_xn + (size_t)row * DM);
    oh[2*threadIdx.x]         = __floats2half2_rn(v0.x*scl*w0.x, v0.y*scl*w0.y);
    oh[2*threadIdx.x+1]       = __floats2half2_rn(v0.z*scl*w0.z, v0.w*scl*w0.w);
    oh[2*(threadIdx.x+256)]   = __floats2half2_rn(v1.x*scl*w1.x, v1.y*scl*w1.y);
    oh[2*(threadIdx.x+256)+1] = __floats2half2_rn(v1.z*scl*w1.z, v1.w*scl*w1.w);
}

// ---------------- weight transpose to fp16 ----------------
__global__ __launch_bounds__(256) void wtrans_kernel(const float* __restrict__ W,
                                                     __half* __restrict__ Th,
                                                     int K, int N) {
    __shared__ float s[32][33];
    int tx = threadIdx.x & 31, ty = threadIdx.x >> 5;
    int n0 = blockIdx.x * 32, k0 = blockIdx.y * 32;
    #pragma unroll
    for (int i = 0; i < 4; i++)
        s[ty + i*8][tx] = W[(size_t)(k0 + ty + i*8) * N + n0 + tx];
    __syncthreads();
    #pragma unroll
    for (int i = 0; i < 4; i++) {
        int n = n0 + ty + i*8;
        Th[(size_t)n * K + k0 + tx] = __float2half_rn(s[tx][ty + i*8]);
    }
}

// ---------------- RoPE cos/sin table ----------------
__global__ void rope_table_kernel() {
    int idx = blockIdx.x * blockDim.x + threadIdx.x;
    if (idx >= SEQ * NROT) return;
    int s = idx >> 6;
    int i = idx & 63;
    double invf = pow(10000.0, -(double)(2*i) / (double)HDIM);
    double ang = (double)s * invf;
    g_cos[idx] = (float)cos(ang);
    g_sin[idx] = (float)sin(ang);
}

// ================= mma.sync fp16 GEMM, 1-pass =================
// C[M,N] = A[M,K] * B^T[N,K]. CTA 128x128, K-chunk 32, 4 stages, 2 CTAs/SM.
// ROPE: apply RoPE (+oscale) to output pairs. OT: __half or float.
#define GK       32
#define ROWB     80u
#define TILEP    (128u * ROWB)              // 10240 B
#define NSTAGE   4
#define STAGEB   (2u * TILEP)               // A, B
#define GEMM_SMEM (NSTAGE * STAGEB)         // 81920

template<typename OT, bool ROPE>
__global__ __launch_bounds__(256, 2) void hgemm_kernel(
        const __half* __restrict__ A, const __half* __restrict__ B,
        OT* __restrict__ C, int N, int Kd, float oscale) {
    extern __shared__ char smem[];
    const uint32_t sb = smem_to_u32(smem);
    const int tid  = threadIdx.x;
    const int lane = tid & 31, wid = tid >> 5;
    const int bm = blockIdx.y * 128, bn = blockIdx.x * 128;
    const int wm = (wid & 3) * 32, wn = (wid >> 2) * 64;
    const int NCH = Kd / GK;

    const int lr = tid >> 2;
    const int colel = (tid & 3) * 8;
    const uint32_t so_base = (uint32_t)(tid & 3) * 16u;

    uint32_t aoff[2], boff[4];
    #pragma unroll
    for (int mi = 0; mi < 2; mi++)
        aoff[mi] = (uint32_t)(wm + mi*16 + (lane & 15)) * ROWB + ((uint32_t)(lane >> 4) << 4);
    #pragma unroll
    for (int f = 0; f < 4; f++) {
        int rb = wn + f*16 + (lane & 7) + ((lane >> 4) << 3);
        boff[f] = (uint32_t)rb * ROWB + (((uint32_t)(lane >> 3) & 1u) << 4);
    }

    float acc[2][8][4];
    #pragma unroll
    for (int mi = 0; mi < 2; mi++)
        #pragma unroll
        for (int ni = 0; ni < 8; ni++)
            #pragma unroll
            for (int c = 0; c < 4; c++) acc[mi][ni][c] = 0.f;

    auto load_chunk = [&](int stage, int k0) {
        uint32_t s0 = sb + (uint32_t)stage * STAGEB;
        #pragma unroll
        for (int h = 0; h < 2; h++) {
            int r = lr + h * 64;
            uint32_t so = (uint32_t)r * ROWB + so_base;
            cp_async16(s0 + so,         A + (size_t)(bm + r) * Kd + k0 + colel);
            cp_async16(s0 + TILEP + so, B + (size_t)(bn + r) * Kd + k0 + colel);
        }
    };

    auto compute = [&](int stage) {
        uint32_t s0 = sb + (uint32_t)stage * STAGEB;
        #pragma unroll
        for (int ks = 0; ks < 2; ks++) {
            uint32_t ah[2][4], bh[4][4];
            #pragma unroll
            for (int mi = 0; mi < 2; mi++)
                ldm_x4(ah[mi], s0 + aoff[mi] + ks*32);
            #pragma unroll
            for (int f = 0; f < 4; f++)
                ldm_x4(bh[f], s0 + TILEP + boff[f] + ks*32);
            #pragma unroll
            for (int mi = 0; mi < 2; mi++)
                #pragma unroll
                for (int f = 0; f < 4; f++) {
                    mma16816(acc[mi][2*f],   ah[mi], &bh[f][0]);
                    mma16816(acc[mi][2*f+1], ah[mi], &bh[f][2]);
                }
        }
    };

    load_chunk(0, 0);      CP_COMMIT();
    load_chunk(1, GK);     CP_COMMIT();
    load_chunk(2, 2*GK);   CP_COMMIT();

    for (int i = 0; i < NCH; i++) {
        if (i < NCH - 2)       CP_WAIT(2);
        else if (i == NCH - 2) CP_WAIT(1);
        else                   CP_WAIT(0);
        __syncthreads();
        if (i + 3 < NCH) { load_chunk((i + 3) % NSTAGE, (i + 3) * GK); CP_COMMIT(); }
        compute(i % NSTAGE);
    }

    #pragma unroll
    for (int mi = 0; mi < 2; mi++) {
        int row = bm + wm + mi*16 + (lane >> 2);
        #pragma unroll
        for (int ni = 0; ni < 8; ni++) {
            int col = bn + wn + ni*8 + (lane & 3)*2;
            float r0 = acc[mi][ni][0], r1 = acc[mi][ni][1];
            float r2 = acc[mi][ni][2], r3 = acc[mi][ni][3];
            if (ROPE) {
                int i2 = (col & (HDIM-1)) >> 1;
                int s0i = ((row & (SEQ-1)) << 6) + i2;
                int s1i = (((row + 8) & (SEQ-1)) << 6) + i2;
                float c0 = g_cos[s0i], sn0 = g_sin[s0i];
                float c1 = g_cos[s1i], sn1 = g_sin[s1i];
                float e0 = r0, o0 = r1, e1 = r2, o1 = r3;
                r0 = (e0*c0 - o0*sn0) * oscale;
                r1 = (e0*sn0 + o0*c0) * oscale;
                r2 = (e1*c1 - o1*sn1) * oscale;
                r3 = (e1*sn1 + o1*c1) * oscale;
            }
            OT* p = C + (size_t)row * N + col;
            if (sizeof(OT) == 2) {
                *(__half2*)p           = __floats2half2_rn(r0, r1);
                *(__half2*)(p + 8*N)   = __floats2half2_rn(r2, r3);
            } else {
                *(float2*)p            = make_float2(r0, r1);
                *(float2*)(p + 8*N)    = make_float2(r2, r3);
            }
        }
    }
}

// ================= tensor-core flash attention (1-pass fp16) =================
// q/k/v already fp16 (rope+scale pre-applied). 3 smem tiles: Q, K, V.
#define ATS   136
#define ATSB  272u
#define AT_TILE (64*ATS*2)       // 17408 B
#define QS_OFF 0
#define KS_OFF AT_TILE
#define VS_OFF (2*AT_TILE)
#define ATT_SMEM (3*AT_TILE)     // 52224

__global__ __launch_bounds__(128, 3) void attn_kernel(const __half* __restrict__ Q,
                                                      const __half* __restrict__ K,
                                                      const __half* __restrict__ V) {
    extern __shared__ char smem[];
    const uint32_t sb = smem_to_u32(smem);

    const int tid = threadIdx.x;
    const int lane = tid & 31, w = tid >> 5;
    const int qt = blockIdx.x, h = blockIdx.y, b = blockIdx.z;
    const int kh = h >> 2;
    const int qstart = qt * 64;

    // ---- load Q tile (fp16, 16B chunks) ----
    for (int it = tid; it < 64*16; it += 128) {
        int r = it >> 4, c = it & 15;
        const __half* qp = Q + (((size_t)b*SEQ + qstart + r)*NH + h)*HDIM + c*8;
        *(float4*)(smem + QS_OFF + r*ATSB + c*16) = *(const float4*)qp;
    }

    const uint32_t qa_ad = sb + QS_OFF
        + (uint32_t)(w*16 + (lane & 15)) * ATSB + ((uint32_t)(lane >> 4) << 4);
    uint32_t kb_ad[4];
    #pragma unroll
    for (int f = 0; f < 4; f++)
        kb_ad[f] = sb + KS_OFF + (uint32_t)(f*16 + (lane & 7) + ((lane >> 4) << 3)) * ATSB
                 + (((uint32_t)(lane >> 3) & 1u) << 4);
    const uint32_t v_row = (uint32_t)((lane & 7) + (((lane >> 3) & 1) << 3));
    const uint32_t v_colsh = ((uint32_t)(lane >> 4) & 1u) << 4;

    const int qrow0 = qstart + w*16 + (lane >> 2);

    float oacc[16][4];
    #pragma unroll
    for (int t = 0; t < 16; t++)
        #pragma unroll
        for (int e = 0; e < 4; e++) oacc[t][e] = 0.f;
    float m0 = -3.0e38f, m1 = -3.0e38f, l0 = 0.f, l1 = 0.f;

    int kmin = qstart - WIN; if (kmin < 0) kmin = 0;
    const int kmax = qstart + 63;

    for (int k0 = kmin; k0 <= kmax; k0 += 64) {
        __syncthreads();   // prior-tile smem reads done
        // ---- K/V tiles via cp.async ----
        for (int it = tid; it < 64*16; it += 128) {
            int r = it >> 4, c = it & 15;
            size_t gofs = (((size_t)b*SEQ + k0 + r)*NKH + kh)*HDIM + c*8;
            uint32_t so = (uint32_t)r * ATSB + (uint32_t)c * 16u;
            cp_async16(sb + KS_OFF + so, K + gofs);
            cp_async16(sb + VS_OFF + so, V + gofs);
        }
        CP_COMMIT();
        CP_WAIT(0);
        __syncthreads();

        // ---- S = Q K^T (1-pass) ----
        float sacc[8][4];
        #pragma unroll
        for (int t = 0; t < 8; t++)
            #pragma unroll
            for (int e = 0; e < 4; e++) sacc[t][e] = 0.f;

        #pragma unroll
        for (int ks = 0; ks < 8; ks++) {
            uint32_t qa[4];
            ldm_x4(qa, qa_ad + ks*32);
            #pragma unroll
            for (int f = 0; f < 4; f++) {
                uint32_t kb[4];
                ldm_x4(kb, kb_ad[f] + ks*32);
                mma16816(sacc[2*f],   qa, &kb[0]);
                mma16816(sacc[2*f+1], qa, &kb[2]);
            }
        }

        // ---- mask ----
        #pragma unroll
        for (int t = 0; t < 8; t++) {
            int kvb = k0 + t*8 + 2*(lane & 3);
            #pragma unroll
            for (int e = 0; e < 4; e++) {
                int qp = qrow0 + ((e >> 1) << 3);
                int dlt = qp - (kvb + (e & 1));
                if (dlt < 0 || dlt > WIN) sacc[t][e] = -3.0e38f;
            }
        }

        // ---- online softmax ----
        float mt0 = -3.0e38f, mt1 = -3.0e38f;
        #pragma unroll
        for (int t = 0; t < 8; t++) {
            mt0 = fmaxf(mt0, fmaxf(sacc[t][0], sacc[t][1]));
            mt1 = fmaxf(mt1, fmaxf(sacc[t][2], sacc[t][3]));
        }
        mt0 = fmaxf(mt0, __shfl_xor_sync(0xffffffffu, mt0, 1));
        mt0 = fmaxf(mt0, __shfl_xor_sync(0xffffffffu, mt0, 2));
        mt1 = fmaxf(mt1, __shfl_xor_sync(0xffffffffu, mt1, 1));
        mt1 = fmaxf(mt1, __shfl_xor_sync(0xffffffffu, mt1, 2));
        float m0n = fmaxf(m0, mt0), m1n = fmaxf(m1, mt1);
        float al0 = __expf(m0 - m0n), al1 = __expf(m1 - m1n);
        m0 = m0n; m1 = m1n;
        float s0 = 0.f, s1 = 0.f;
        #pragma unroll
        for (int t = 0; t < 8; t++) {
            sacc[t][0] = __expf(sacc[t][0] - m0n);
            sacc[t][1] = __expf(sacc[t][1] - m0n);
            sacc[t][2] = __expf(sacc[t][2] - m1n);
            sacc[t][3] = __expf(sacc[t][3] - m1n);
            s0 += sacc[t][0] + sacc[t][1];
            s1 += sacc[t][2] + sacc[t][3];
        }
        s0 += __shfl_xor_sync(0xffffffffu, s0, 1);
        s0 += __shfl_xor_sync(0xffffffffu, s0, 2);
        s1 += __shfl_xor_sync(0xffffffffu, s1, 1);
        s1 += __shfl_xor_sync(0xffffffffu, s1, 2);
        l0 = l0 * al0 + s0;
        l1 = l1 * al1 + s1;
        #pragma unroll
        for (int t = 0; t < 16; t++) {
            oacc[t][0] *= al0; oacc[t][1] *= al0;
            oacc[t][2] *= al1; oacc[t][3] *= al1;
        }

        // ---- O += P V (1-pass) ----
        #pragma unroll
        for (int u = 0; u < 4; u++) {
            uint32_t aph[4];
            #pragma unroll
            for (int half_t = 0; half_t < 2; half_t++) {
                int t = 2*u + half_t;
                aph[0 + 2*half_t] = pack_h2(__float2half_rn(sacc[t][0]), __float2half_rn(sacc[t][1]));
                aph[1 + 2*half_t] = pack_h2(__float2half_rn(sacc[t][2]), __float2half_rn(sacc[t][3]));
            }
            #pragma unroll
            for (int f2 = 0; f2 < 8; f2++) {
                uint32_t bv[4];
                ldm_x4_t(bv, sb + VS_OFF + (u*16 + v_row) * ATSB + (uint32_t)f2*32 + v_colsh);
                mma16816(oacc[2*f2],   aph, &bv[0]);
                mma16816(oacc[2*f2+1], aph, &bv[2]);
            }
        }
    }

    // ---- epilogue: normalize, store fp16 ----
    float inv0 = 1.0f / l0, inv1 = 1.0f / l1;
    size_t base0 = (((size_t)b*SEQ + qrow0)*NH + h)*HDIM;
    size_t base1 = (((size_t)b*SEQ + qrow0 + 8)*NH + h)*HDIM;
    #pragma unroll
    for (int t = 0; t < 16; t++) {
        int d = t*8 + 2*(lane & 3);
        *(__half2*)(g_ao + base0 + d) = __floats2half2_rn(oacc[t][0]*inv0, oacc[t][1]*inv0);
        *(__half2*)(g_ao + base1 + d) = __floats2half2_rn(oacc[t][2]*inv1, oacc[t][3]*inv1);
    }
}

// ---------------- launcher ----------------
extern "C" void kernel_launch(void* const* d_in, const int* in_sizes, int n_in,
                              void* d_out, int out_size) {
    (void)in_sizes; (void)n_in; (void)out_size;
    const float* x    = (const float*)d_in[0];
    const float* ln_w = (const float*)d_in[1];
    const float* wq   = (const float*)d_in[2];
    const float* wk   = (const float*)d_in[3];
    const float* wv   = (const float*)d_in[4];
    const float* wo   = (const float*)d_in[5];
    float* out = (float*)d_out;

    __half *p_q, *p_k, *p_v, *p_xn, *p_ao, *p_wq, *p_wk, *p_wv, *p_wo;
    cudaGetSymbolAddress((void**)&p_q,  g_q);
    cudaGetSymbolAddress((void**)&p_k,  g_k);
    cudaGetSymbolAddress((void**)&p_v,  g_v);
    cudaGetSymbolAddress((void**)&p_xn, g_xn);
    cudaGetSymbolAddress((void**)&p_ao, g_ao);
    cudaGetSymbolAddress((void**)&p_wq, g_wqT);
    cudaGetSymbolAddress((void**)&p_wk, g_wkT);
    cudaGetSymbolAddress((void**)&p_wv, g_wvT);
    cudaGetSymbolAddress((void**)&p_wo, g_woT);

    cudaFuncSetAttribute(attn_kernel, cudaFuncAttributeMaxDynamicSharedMemorySize, ATT_SMEM);
    cudaFuncSetAttribute(hgemm_kernel<__half,true>,  cudaFuncAttributeMaxDynamicSharedMemorySize, GEMM_SMEM);
    cudaFuncSetAttribute(hgemm_kernel<__half,false>, cudaFuncAttributeMaxDynamicSharedMemorySize, GEMM_SMEM);
    cudaFuncSetAttribute(hgemm_kernel<float,false>,  cudaFuncAttributeMaxDynamicSharedMemorySize, GEMM_SMEM);

    const float qscale = 0.08838834764831845f;   // 1/sqrt(128), folded into q

    rmsnorm_kernel<<<MTOT, 256>>>(x, ln_w);                                     // 1
    rope_table_kernel<<<(SEQ*NROT + 255)/256, 256>>>();                         // 2
    wtrans_kernel<<<dim3(DM/32, DM/32), 256>>>(wq, p_wq, DM, DM);               // 3
    wtrans_kernel<<<dim3((NKH*HDIM)/32, DM/32), 256>>>(wk, p_wk, DM, NKH*HDIM); // 4
    wtrans_kernel<<<dim3((NKH*HDIM)/32, DM/32), 256>>>(wv, p_wv, DM, NKH*HDIM); // 5
    hgemm_kernel<__half,true><<<dim3(DM/128, MTOT/128), 256, GEMM_SMEM>>>(
        p_xn, p_wq, p_q, DM, DM, qscale);                                       // 6 <- profiled
    hgemm_kernel<__half,true><<<dim3((NKH*HDIM)/128, MTOT/128), 256, GEMM_SMEM>>>(
        p_xn, p_wk, p_k, NKH*HDIM, DM, 1.0f);                                   // 7
    hgemm_kernel<__half,false><<<dim3((NKH*HDIM)/128, MTOT/128), 256, GEMM_SMEM>>>(
        p_xn, p_wv, p_v, NKH*HDIM, DM, 1.0f);                                   // 8
    attn_kernel<<<dim3(SEQ/64, NH, BC), 128, ATT_SMEM>>>(p_q, p_k, p_v);        // 9
    wtrans_kernel<<<dim3(DM/32, DM/32), 256>>>(wo, p_wo, DM, DM);               // 10
    hgemm_kernel<float,false><<<dim3(DM/128, MTOT/128), 256, GEMM_SMEM>>>(
        p_ao, p_wo, out, DM, DM, 1.0f);                                         // 11
}